// round 1
// baseline (speedup 1.0000x reference)
#include <cuda_runtime.h>
#include <cuda_bf16.h>
#include <cstdint>

// Problem constants
#define BATCH 4
#define SEQL 1024
#define HIDDEN 1024
#define NQH 32          // query heads
#define NKVH 16         // kv heads
#define HDIM 64
#define QKV_COLS 4096   // 2048 q + 1024 k + 1024 v
#define ATTN_COLS 2048  // 32*64
#define ROWS 4096       // BATCH*SEQL

// Scratch (allocation-free rule: __device__ globals)
__device__ float g_qkv[(size_t)ROWS * QKV_COLS];   // 64 MB
__device__ float g_attn[(size_t)ROWS * ATTN_COLS]; // 32 MB

// ---------------------------------------------------------------------------
// Classic fp32 SGEMM: BM=128, BN=128, BK=16, 256 threads, 8x8 per thread.
// C[M,N] = A[M,K] @ B[K,N], all row-major, dims divisible by tile sizes.
// ---------------------------------------------------------------------------
template <int M, int N, int K>
__device__ __forceinline__ void sgemm_body(const float* __restrict__ A,
                                           const float* __restrict__ B,
                                           float* __restrict__ C) {
    __shared__ float As[16][128];   // transposed A tile: As[k][m]
    __shared__ float Bs[16][128];   // Bs[k][n]

    const int tid = threadIdx.x;
    const int tx = tid & 15;        // 0..15 -> N direction
    const int ty = tid >> 4;        // 0..15 -> M direction
    const int brow = blockIdx.y * 128;
    const int bcol = blockIdx.x * 128;

    float acc[8][8];
#pragma unroll
    for (int i = 0; i < 8; i++)
#pragma unroll
        for (int j = 0; j < 8; j++) acc[i][j] = 0.f;

    for (int kk = 0; kk < K; kk += 16) {
        // Load A tile (128 rows x 16 k) and B tile (16 k x 128 cols), float4.
#pragma unroll
        for (int u = 0; u < 2; u++) {
            int f = tid + u * 256;          // 0..511
            int ar = f >> 2;                // 0..127
            int ac = (f & 3) << 2;          // 0,4,8,12
            float4 av = *(const float4*)(A + (size_t)(brow + ar) * K + kk + ac);
            As[ac + 0][ar] = av.x;
            As[ac + 1][ar] = av.y;
            As[ac + 2][ar] = av.z;
            As[ac + 3][ar] = av.w;
            int br = f >> 5;                // 0..15
            int bc = (f & 31) << 2;         // 0..124
            float4 bv = *(const float4*)(B + (size_t)(kk + br) * N + bcol + bc);
            *(float4*)&Bs[br][bc] = bv;
        }
        __syncthreads();

#pragma unroll
        for (int k = 0; k < 16; k++) {
            float ra[8], rb[8];
            *(float4*)&ra[0] = *(const float4*)&As[k][ty * 8];
            *(float4*)&ra[4] = *(const float4*)&As[k][ty * 8 + 4];
            *(float4*)&rb[0] = *(const float4*)&Bs[k][tx * 8];
            *(float4*)&rb[4] = *(const float4*)&Bs[k][tx * 8 + 4];
#pragma unroll
            for (int i = 0; i < 8; i++)
#pragma unroll
                for (int j = 0; j < 8; j++) acc[i][j] += ra[i] * rb[j];
        }
        __syncthreads();
    }

#pragma unroll
    for (int i = 0; i < 8; i++) {
        size_t row = (size_t)(brow + ty * 8 + i);
        float4* cp = (float4*)(C + row * N + bcol + tx * 8);
        cp[0] = make_float4(acc[i][0], acc[i][1], acc[i][2], acc[i][3]);
        cp[1] = make_float4(acc[i][4], acc[i][5], acc[i][6], acc[i][7]);
    }
}

__global__ __launch_bounds__(256) void qkv_gemm_kernel(const float* __restrict__ A,
                                                       const float* __restrict__ B) {
    sgemm_body<ROWS, QKV_COLS, HIDDEN>(A, B, g_qkv);
}

__global__ __launch_bounds__(256) void out_gemm_kernel(const float* __restrict__ B,
                                                       float* __restrict__ C) {
    sgemm_body<ROWS, HIDDEN, ATTN_COLS>(g_attn, B, C);
}

// ---------------------------------------------------------------------------
// Flash-attention (fp32, CUDA cores): 64x64 Q/KV tiles, online softmax,
// causal + ALiBi. Grid: (SEQ/64, BATCH*NQH), 256 threads.
// Per thread: 4 q-rows (ty*4+i) x 4 strided kv-cols / head-dims (tx+16*j).
// ---------------------------------------------------------------------------
#define QS_OFF 0
#define KS_OFF (64 * 65)
#define VS_OFF (2 * 64 * 65)
#define PS_OFF (3 * 64 * 65)
#define RM_OFF (4 * 64 * 65)
#define RL_OFF (4 * 64 * 65 + 64 * 17)
#define ATTN_SMEM_FLOATS (4 * 64 * 65 + 2 * 64 * 17)
#define ATTN_SMEM_BYTES (ATTN_SMEM_FLOATS * 4)

__global__ __launch_bounds__(256) void attn_kernel() {
    extern __shared__ float sm[];
    float* Qs = sm + QS_OFF;   // [64][65]
    float* Ks = sm + KS_OFF;   // [64][65]
    float* Vs = sm + VS_OFF;   // [64][65]
    float* Ps = sm + PS_OFF;   // [64][65]
    float* Rm = sm + RM_OFF;   // [64][17]
    float* Rl = sm + RL_OFF;   // [64][17]

    const int qblk = blockIdx.x;
    const int bh = blockIdx.y;
    const int b = bh >> 5;
    const int h = bh & 31;
    const int kvh = h >> 1;                       // GQA repeat_interleave(2)
    const float slope = exp2f(-0.25f * (float)(h + 1));
    const int q0 = qblk * 64;

    const int tid = threadIdx.x;
    const int tx = tid & 15;
    const int ty = tid >> 4;

    // Load Q tile: Qs[r][d] = qkv[b*S+q0+r][h*64+d]
    for (int i = tid; i < 4096; i += 256) {
        int rr = i >> 6, d = i & 63;
        Qs[rr * 65 + d] = g_qkv[(size_t)(b * SEQL + q0 + rr) * QKV_COLS + h * 64 + d];
    }

    float m[4], l[4], o[4][4];
#pragma unroll
    for (int i = 0; i < 4; i++) {
        m[i] = -1e30f;
        l[i] = 0.f;
#pragma unroll
        for (int j = 0; j < 4; j++) o[i][j] = 0.f;
    }

    for (int kb = 0; kb <= qblk; kb++) {
        const int k0 = kb * 64;
        __syncthreads();  // prior iter's Ps/Vs/Rm/Rl reads complete
        for (int i = tid; i < 4096; i += 256) {
            int rr = i >> 6, d = i & 63;
            size_t base = (size_t)(b * SEQL + k0 + rr) * QKV_COLS;
            Ks[rr * 65 + d] = g_qkv[base + 2048 + kvh * 64 + d];
            Vs[rr * 65 + d] = g_qkv[base + 3072 + kvh * 64 + d];
        }
        __syncthreads();

        // Scores S = Q K^T
        float s[4][4];
#pragma unroll
        for (int i = 0; i < 4; i++)
#pragma unroll
            for (int j = 0; j < 4; j++) s[i][j] = 0.f;

#pragma unroll 8
        for (int d = 0; d < 64; d++) {
            float qv[4], kv[4];
#pragma unroll
            for (int i = 0; i < 4; i++) qv[i] = Qs[(ty * 4 + i) * 65 + d];
#pragma unroll
            for (int j = 0; j < 4; j++) kv[j] = Ks[(tx + 16 * j) * 65 + d];
#pragma unroll
            for (int i = 0; i < 4; i++)
#pragma unroll
                for (int j = 0; j < 4; j++) s[i][j] += qv[i] * kv[j];
        }

        // scale + ALiBi + causal mask, local row max
        float mloc[4];
#pragma unroll
        for (int i = 0; i < 4; i++) {
            mloc[i] = -1e30f;
            int qp = q0 + ty * 4 + i;
#pragma unroll
            for (int j = 0; j < 4; j++) {
                int kp = k0 + tx + 16 * j;
                if (kp <= qp)
                    s[i][j] = s[i][j] * 0.125f + slope * (float)(kp - qp);
                else
                    s[i][j] = -1e30f;
                mloc[i] = fmaxf(mloc[i], s[i][j]);
            }
            Rm[(ty * 4 + i) * 17 + tx] = mloc[i];
        }
        __syncthreads();

        float corr[4];
#pragma unroll
        for (int i = 0; i < 4; i++) {
            int r = ty * 4 + i;
            float mm = m[i];
#pragma unroll
            for (int k = 0; k < 16; k++) mm = fmaxf(mm, Rm[r * 17 + k]);
            corr[i] = __expf(m[i] - mm);
            m[i] = mm;
            float ll = 0.f;
#pragma unroll
            for (int j = 0; j < 4; j++) {
                float p = __expf(s[i][j] - mm);
                Ps[r * 65 + tx + 16 * j] = p;
                ll += p;
            }
            Rl[r * 17 + tx] = ll;
#pragma unroll
            for (int j = 0; j < 4; j++) o[i][j] *= corr[i];
        }
        __syncthreads();  // Ps and Rl visible; Rm reads complete

#pragma unroll
        for (int i = 0; i < 4; i++) {
            int r = ty * 4 + i;
            float ls = 0.f;
#pragma unroll
            for (int k = 0; k < 16; k++) ls += Rl[r * 17 + k];
            l[i] = l[i] * corr[i] + ls;
        }

        // O += P V
#pragma unroll 8
        for (int c = 0; c < 64; c++) {
            float pv[4], vv[4];
#pragma unroll
            for (int i = 0; i < 4; i++) pv[i] = Ps[(ty * 4 + i) * 65 + c];
#pragma unroll
            for (int j = 0; j < 4; j++) vv[j] = Vs[c * 65 + tx + 16 * j];
#pragma unroll
            for (int i = 0; i < 4; i++)
#pragma unroll
                for (int j = 0; j < 4; j++) o[i][j] += pv[i] * vv[j];
        }
    }

    // Epilogue: normalize and store to g_attn[b*S+q][h*64+d]
#pragma unroll
    for (int i = 0; i < 4; i++) {
        float inv = 1.f / l[i];
        size_t row = (size_t)(b * SEQL + q0 + ty * 4 + i);
#pragma unroll
        for (int j = 0; j < 4; j++) {
            g_attn[row * ATTN_COLS + h * 64 + tx + 16 * j] = o[i][j] * inv;
        }
    }
}

// ---------------------------------------------------------------------------
extern "C" void kernel_launch(void* const* d_in, const int* in_sizes, int n_in,
                              void* d_out, int out_size) {
    const float* inputs = (const float*)d_in[0];  // [4,1024,1024]
    const float* W_qkv  = (const float*)d_in[1];  // [1024,4096]
    const float* W_out  = (const float*)d_in[2];  // [2048,1024]
    float* out = (float*)d_out;                   // [4,1024,1024]

    // Opt-in dynamic smem (>48KB). Host-side attribute set; not a stream op,
    // safe under graph capture; idempotent.
    cudaFuncSetAttribute(attn_kernel,
                         cudaFuncAttributeMaxDynamicSharedMemorySize,
                         ATTN_SMEM_BYTES);

    // 1) QKV projection: [4096,1024] @ [1024,4096] -> g_qkv
    qkv_gemm_kernel<<<dim3(QKV_COLS / 128, ROWS / 128), 256>>>(inputs, W_qkv);

    // 2) Attention -> g_attn
    attn_kernel<<<dim3(SEQL / 64, BATCH * NQH), 256, ATTN_SMEM_BYTES>>>();

    // 3) Output projection: [4096,2048] @ [2048,1024] -> out
    out_gemm_kernel<<<dim3(HIDDEN / 128, ROWS / 128), 256>>>(W_out, out);
}

// round 3
// speedup vs baseline: 1.5041x; 1.5041x over previous
#include <cuda_runtime.h>
#include <cuda_bf16.h>
#include <cstdint>

// Problem constants
#define BATCH 4
#define SEQL 1024
#define HIDDEN 1024
#define QKV_COLS 4096   // 2048 q + 1024 k + 1024 v
#define ATTN_COLS 2048  // 32*64
#define ROWS 4096       // BATCH*SEQL

// ---------------------------------------------------------------------------
// Scratch (__device__ globals; allocation-free rule)
// ---------------------------------------------------------------------------
__device__ float g_qkv[(size_t)ROWS * QKV_COLS];    // 64 MB
__device__ float g_attn[(size_t)ROWS * ATTN_COLS];  // 32 MB
__device__ __nv_bfloat16 g_Ahi[(size_t)ROWS * HIDDEN];
__device__ __nv_bfloat16 g_Alo[(size_t)ROWS * HIDDEN];
__device__ __nv_bfloat16 g_Wqkv_hi[(size_t)QKV_COLS * HIDDEN];  // [N,K]
__device__ __nv_bfloat16 g_Wqkv_lo[(size_t)QKV_COLS * HIDDEN];
__device__ __nv_bfloat16 g_At2hi[(size_t)ROWS * ATTN_COLS];
__device__ __nv_bfloat16 g_At2lo[(size_t)ROWS * ATTN_COLS];
__device__ __nv_bfloat16 g_Wout_hi[(size_t)HIDDEN * ATTN_COLS]; // [N,K]
__device__ __nv_bfloat16 g_Wout_lo[(size_t)HIDDEN * ATTN_COLS];

// ---------------------------------------------------------------------------
// PTX helpers (sm_80+ only — NO tcgen05; harness targets compute_103)
// ---------------------------------------------------------------------------
__device__ __forceinline__ uint32_t smem_u32(const void* p) {
    uint32_t a;
    asm("{ .reg .u64 t; cvta.to.shared.u64 t, %1; cvt.u32.u64 %0, t; }" : "=r"(a) : "l"(p));
    return a;
}
__device__ __forceinline__ void cp16(uint32_t dst, const void* src) {
    asm volatile("cp.async.cg.shared.global [%0], [%1], 16;" :: "r"(dst), "l"(src));
}
#define CP_COMMIT() asm volatile("cp.async.commit_group;" ::: "memory")
#define CP_WAIT1()  asm volatile("cp.async.wait_group 1;" ::: "memory")

__device__ __forceinline__ uint32_t lds32(uint32_t a) {
    uint32_t v;
    asm volatile("ld.shared.b32 %0, [%1];" : "=r"(v) : "r"(a));
    return v;
}

// mma.sync m16n8k16 row.col bf16 -> fp32 accumulate
__device__ __forceinline__ void mma_bf16(float* d, const uint32_t* a, const uint32_t* b) {
    asm volatile(
        "mma.sync.aligned.m16n8k16.row.col.f32.bf16.bf16.f32 "
        "{%0,%1,%2,%3}, {%4,%5,%6,%7}, {%8,%9}, {%0,%1,%2,%3};"
        : "+f"(d[0]), "+f"(d[1]), "+f"(d[2]), "+f"(d[3])
        : "r"(a[0]), "r"(a[1]), "r"(a[2]), "r"(a[3]), "r"(b[0]), "r"(b[1]));
}

// ---------------------------------------------------------------------------
// HMMA GEMM: C[M,N](fp32) = A[M,K] * B[N,K]^T with bf16 hi/lo 3-product split.
// CTA tile 128x128, BK=32, 256 threads (8 warps: 2(M) x 4(N), warp tile 64x32).
// Smem row stride 40 bf16 (80B) -> conflict-free 32-bit fragment loads.
// ---------------------------------------------------------------------------
#define RSTRIDE 40                         // bf16 elems per smem row (32 + 8 pad)
#define SLAB (128 * RSTRIDE * 2)           // 10240 B per matrix slab
#define STAGE (4 * SLAB)                   // Ahi, Alo, Bhi, Blo = 40960 B
#define GSM_TOTAL (2 * STAGE)              // double buffer = 81920 B

__global__ __launch_bounds__(256)
void gemm_tc_kernel(const __nv_bfloat16* __restrict__ Ahi,
                    const __nv_bfloat16* __restrict__ Alo,
                    const __nv_bfloat16* __restrict__ Bhi,
                    const __nv_bfloat16* __restrict__ Blo,
                    float* __restrict__ C, int Ndim, int Kdim) {
    extern __shared__ __align__(256) char smem[];
    const uint32_t sbase = smem_u32(smem);
    const int tid = threadIdx.x;
    const int lane = tid & 31;
    const int warp = tid >> 5;
    const int wm = warp & 1;                // 0..1 (M)
    const int wn = warp >> 1;               // 0..3 (N)
    const int brow = blockIdx.y * 128;
    const int bcol = blockIdx.x * 128;

    const __nv_bfloat16* mats[4] = {Ahi, Alo, Bhi, Blo};
    const int KT = Kdim >> 5;               // BK=32 steps

    // Per-thread load slots: 8 cp16 per stage (2048 total / 256 threads)
    const int lrow = tid >> 2;              // 0..63? no: idx mapping below
    (void)lrow;

    auto load_stage = [&](int t) {
        const int s = t & 1;
        const int k0 = t << 5;
        const uint32_t stg = sbase + s * STAGE;
#pragma unroll
        for (int m = 0; m < 4; m++) {
            const int rowbase = (m < 2) ? brow : bcol;
            const __nv_bfloat16* base = mats[m];
#pragma unroll
            for (int u = 0; u < 2; u++) {
                int idx = tid + u * 256;        // 0..511
                int row = idx >> 2;             // 0..127
                int seg = idx & 3;              // 0..3 (8 bf16 each)
                const __nv_bfloat16* src =
                    base + (size_t)(rowbase + row) * Kdim + k0 + seg * 8;
                uint32_t dst = stg + m * SLAB + row * (RSTRIDE * 2) + seg * 16;
                cp16(dst, src);
            }
        }
        CP_COMMIT();
    };

    float acc[4][4][4];
#pragma unroll
    for (int i = 0; i < 4; i++)
#pragma unroll
        for (int j = 0; j < 4; j++)
#pragma unroll
            for (int r = 0; r < 4; r++) acc[i][j][r] = 0.f;

    load_stage(0);
    if (KT > 1) load_stage(1); else CP_COMMIT();

    const int r0 = lane >> 2;               // 0..7
    const int cpair = (lane & 3) * 2;       // 0,2,4,6

    for (int t = 0; t < KT; t++) {
        CP_WAIT1();
        __syncthreads();
        const uint32_t stg = sbase + (t & 1) * STAGE;
        const uint32_t aHi = stg + (wm * 64) * (RSTRIDE * 2);
        const uint32_t aLo = aHi + SLAB;
        const uint32_t bHi = stg + 2 * SLAB + (wn * 32) * (RSTRIDE * 2);
        const uint32_t bLo = bHi + SLAB;

#pragma unroll
        for (int ks = 0; ks < 2; ks++) {
            const uint32_t colb = ks * 32 + cpair * 2;   // byte offset of k-pair
            uint32_t ahi[4][4], alo[4][4], bhi[4][2], blo[4][2];
#pragma unroll
            for (int mi = 0; mi < 4; mi++) {
                uint32_t rb = (mi * 16 + r0) * (RSTRIDE * 2);
                ahi[mi][0] = lds32(aHi + rb + colb);
                ahi[mi][1] = lds32(aHi + rb + 8 * (RSTRIDE * 2) + colb);
                ahi[mi][2] = lds32(aHi + rb + colb + 16);
                ahi[mi][3] = lds32(aHi + rb + 8 * (RSTRIDE * 2) + colb + 16);
                alo[mi][0] = lds32(aLo + rb + colb);
                alo[mi][1] = lds32(aLo + rb + 8 * (RSTRIDE * 2) + colb);
                alo[mi][2] = lds32(aLo + rb + colb + 16);
                alo[mi][3] = lds32(aLo + rb + 8 * (RSTRIDE * 2) + colb + 16);
            }
#pragma unroll
            for (int nj = 0; nj < 4; nj++) {
                uint32_t rb = (nj * 8 + r0) * (RSTRIDE * 2);
                bhi[nj][0] = lds32(bHi + rb + colb);
                bhi[nj][1] = lds32(bHi + rb + colb + 16);
                blo[nj][0] = lds32(bLo + rb + colb);
                blo[nj][1] = lds32(bLo + rb + colb + 16);
            }
#pragma unroll
            for (int mi = 0; mi < 4; mi++)
#pragma unroll
                for (int nj = 0; nj < 4; nj++) {
                    mma_bf16(acc[mi][nj], ahi[mi], bhi[nj]);
                    mma_bf16(acc[mi][nj], ahi[mi], blo[nj]);
                    mma_bf16(acc[mi][nj], alo[mi], bhi[nj]);
                }
        }
        __syncthreads();
        if (t + 2 < KT) load_stage(t + 2); else CP_COMMIT();
    }

    // Epilogue: D fragment -> C.  d0,d1 = C[r][c,c+1]; d2,d3 = C[r+8][c,c+1]
#pragma unroll
    for (int mi = 0; mi < 4; mi++) {
        int row = brow + wm * 64 + mi * 16 + r0;
#pragma unroll
        for (int nj = 0; nj < 4; nj++) {
            int col = bcol + wn * 32 + nj * 8 + cpair;
            *(float2*)(C + (size_t)row * Ndim + col) =
                make_float2(acc[mi][nj][0], acc[mi][nj][1]);
            *(float2*)(C + (size_t)(row + 8) * Ndim + col) =
                make_float2(acc[mi][nj][2], acc[mi][nj][3]);
        }
    }
}

// ---------------------------------------------------------------------------
// fp32 -> bf16 hi/lo elementwise split
// ---------------------------------------------------------------------------
__global__ __launch_bounds__(256) void split_kernel(const float* __restrict__ x,
                                                    __nv_bfloat16* __restrict__ hi,
                                                    __nv_bfloat16* __restrict__ lo,
                                                    int n4) {
    int i = blockIdx.x * blockDim.x + threadIdx.x;
    if (i >= n4) return;
    float4 v = ((const float4*)x)[i];
    __nv_bfloat16 h[4], l[4];
    float vv[4] = {v.x, v.y, v.z, v.w};
#pragma unroll
    for (int j = 0; j < 4; j++) {
        h[j] = __float2bfloat16(vv[j]);
        l[j] = __float2bfloat16(vv[j] - __bfloat162float(h[j]));
    }
    ((uint2*)hi)[i] = *(uint2*)h;
    ((uint2*)lo)[i] = *(uint2*)l;
}

// ---------------------------------------------------------------------------
// W[K,N] fp32 -> Wt[N,K] bf16 hi/lo (tiled transpose + split)
// ---------------------------------------------------------------------------
__global__ __launch_bounds__(256) void transpose_split_kernel(
    const float* __restrict__ W, __nv_bfloat16* __restrict__ hi,
    __nv_bfloat16* __restrict__ lo, int K, int N) {
    __shared__ float t[32][33];
    int k0 = blockIdx.y * 32, n0 = blockIdx.x * 32;
    int tx = threadIdx.x, ty = threadIdx.y;  // (32, 8)
#pragma unroll
    for (int j = 0; j < 4; j++)
        t[ty + j * 8][tx] = W[(size_t)(k0 + ty + j * 8) * N + n0 + tx];
    __syncthreads();
#pragma unroll
    for (int j = 0; j < 4; j++) {
        float v = t[tx][ty + j * 8];
        __nv_bfloat16 h = __float2bfloat16(v);
        __nv_bfloat16 l = __float2bfloat16(v - __bfloat162float(h));
        size_t o = (size_t)(n0 + ty + j * 8) * K + k0 + tx;
        hi[o] = h;
        lo[o] = l;
    }
}

// ---------------------------------------------------------------------------
// Flash-attention (fp32, CUDA cores) — unchanged
// ---------------------------------------------------------------------------
#define QS_OFF 0
#define KS_OFF (64 * 65)
#define VS_OFF (2 * 64 * 65)
#define PS_OFF (3 * 64 * 65)
#define RM_OFF (4 * 64 * 65)
#define RL_OFF (4 * 64 * 65 + 64 * 17)
#define ATTN_SMEM_FLOATS (4 * 64 * 65 + 2 * 64 * 17)
#define ATTN_SMEM_BYTES (ATTN_SMEM_FLOATS * 4)

__global__ __launch_bounds__(256) void attn_kernel() {
    extern __shared__ float sm[];
    float* Qs = sm + QS_OFF;
    float* Ks = sm + KS_OFF;
    float* Vs = sm + VS_OFF;
    float* Ps = sm + PS_OFF;
    float* Rm = sm + RM_OFF;
    float* Rl = sm + RL_OFF;

    const int qblk = blockIdx.x;
    const int bh = blockIdx.y;
    const int b = bh >> 5;
    const int h = bh & 31;
    const int kvh = h >> 1;
    const float slope = exp2f(-0.25f * (float)(h + 1));
    const int q0 = qblk * 64;

    const int tid = threadIdx.x;
    const int tx = tid & 15;
    const int ty = tid >> 4;

    for (int i = tid; i < 4096; i += 256) {
        int rr = i >> 6, d = i & 63;
        Qs[rr * 65 + d] = g_qkv[(size_t)(b * SEQL + q0 + rr) * QKV_COLS + h * 64 + d];
    }

    float m[4], l[4], o[4][4];
#pragma unroll
    for (int i = 0; i < 4; i++) {
        m[i] = -1e30f;
        l[i] = 0.f;
#pragma unroll
        for (int j = 0; j < 4; j++) o[i][j] = 0.f;
    }

    for (int kb = 0; kb <= qblk; kb++) {
        const int k0 = kb * 64;
        __syncthreads();
        for (int i = tid; i < 4096; i += 256) {
            int rr = i >> 6, d = i & 63;
            size_t base = (size_t)(b * SEQL + k0 + rr) * QKV_COLS;
            Ks[rr * 65 + d] = g_qkv[base + 2048 + kvh * 64 + d];
            Vs[rr * 65 + d] = g_qkv[base + 3072 + kvh * 64 + d];
        }
        __syncthreads();

        float s[4][4];
#pragma unroll
        for (int i = 0; i < 4; i++)
#pragma unroll
            for (int j = 0; j < 4; j++) s[i][j] = 0.f;

#pragma unroll 8
        for (int d = 0; d < 64; d++) {
            float qv[4], kv[4];
#pragma unroll
            for (int i = 0; i < 4; i++) qv[i] = Qs[(ty * 4 + i) * 65 + d];
#pragma unroll
            for (int j = 0; j < 4; j++) kv[j] = Ks[(tx + 16 * j) * 65 + d];
#pragma unroll
            for (int i = 0; i < 4; i++)
#pragma unroll
                for (int j = 0; j < 4; j++) s[i][j] += qv[i] * kv[j];
        }

        float mloc[4];
#pragma unroll
        for (int i = 0; i < 4; i++) {
            mloc[i] = -1e30f;
            int qp = q0 + ty * 4 + i;
#pragma unroll
            for (int j = 0; j < 4; j++) {
                int kp = k0 + tx + 16 * j;
                if (kp <= qp)
                    s[i][j] = s[i][j] * 0.125f + slope * (float)(kp - qp);
                else
                    s[i][j] = -1e30f;
                mloc[i] = fmaxf(mloc[i], s[i][j]);
            }
            Rm[(ty * 4 + i) * 17 + tx] = mloc[i];
        }
        __syncthreads();

        float corr[4];
#pragma unroll
        for (int i = 0; i < 4; i++) {
            int r = ty * 4 + i;
            float mm = m[i];
#pragma unroll
            for (int k = 0; k < 16; k++) mm = fmaxf(mm, Rm[r * 17 + k]);
            corr[i] = __expf(m[i] - mm);
            m[i] = mm;
            float ll = 0.f;
#pragma unroll
            for (int j = 0; j < 4; j++) {
                float p = __expf(s[i][j] - mm);
                Ps[r * 65 + tx + 16 * j] = p;
                ll += p;
            }
            Rl[r * 17 + tx] = ll;
#pragma unroll
            for (int j = 0; j < 4; j++) o[i][j] *= corr[i];
        }
        __syncthreads();

#pragma unroll
        for (int i = 0; i < 4; i++) {
            int r = ty * 4 + i;
            float ls = 0.f;
#pragma unroll
            for (int k = 0; k < 16; k++) ls += Rl[r * 17 + k];
            l[i] = l[i] * corr[i] + ls;
        }

#pragma unroll 8
        for (int c = 0; c < 64; c++) {
            float pv[4], vv[4];
#pragma unroll
            for (int i = 0; i < 4; i++) pv[i] = Ps[(ty * 4 + i) * 65 + c];
#pragma unroll
            for (int j = 0; j < 4; j++) vv[j] = Vs[c * 65 + tx + 16 * j];
#pragma unroll
            for (int i = 0; i < 4; i++)
#pragma unroll
                for (int j = 0; j < 4; j++) o[i][j] += pv[i] * vv[j];
        }
    }

#pragma unroll
    for (int i = 0; i < 4; i++) {
        float inv = 1.f / l[i];
        size_t row = (size_t)(b * SEQL + q0 + ty * 4 + i);
#pragma unroll
        for (int j = 0; j < 4; j++) {
            g_attn[row * ATTN_COLS + h * 64 + tx + 16 * j] = o[i][j] * inv;
        }
    }
}

// ---------------------------------------------------------------------------
extern "C" void kernel_launch(void* const* d_in, const int* in_sizes, int n_in,
                              void* d_out, int out_size) {
    const float* inputs = (const float*)d_in[0];  // [4,1024,1024]
    const float* W_qkv  = (const float*)d_in[1];  // [1024,4096]
    const float* W_out  = (const float*)d_in[2];  // [2048,1024]
    float* out = (float*)d_out;                   // [4,1024,1024]

    cudaFuncSetAttribute(attn_kernel, cudaFuncAttributeMaxDynamicSharedMemorySize,
                         ATTN_SMEM_BYTES);
    cudaFuncSetAttribute(gemm_tc_kernel, cudaFuncAttributeMaxDynamicSharedMemorySize,
                         GSM_TOTAL);

    __nv_bfloat16 *Ahi, *Alo, *Wqh, *Wql, *A2hi, *A2lo, *Woh, *Wol;
    float *qkv, *attn;
    cudaGetSymbolAddress((void**)&Ahi, g_Ahi);
    cudaGetSymbolAddress((void**)&Alo, g_Alo);
    cudaGetSymbolAddress((void**)&Wqh, g_Wqkv_hi);
    cudaGetSymbolAddress((void**)&Wql, g_Wqkv_lo);
    cudaGetSymbolAddress((void**)&A2hi, g_At2hi);
    cudaGetSymbolAddress((void**)&A2lo, g_At2lo);
    cudaGetSymbolAddress((void**)&Woh, g_Wout_hi);
    cudaGetSymbolAddress((void**)&Wol, g_Wout_lo);
    cudaGetSymbolAddress((void**)&qkv, g_qkv);
    cudaGetSymbolAddress((void**)&attn, g_attn);

    // 1) split inputs, transpose-split W_qkv
    split_kernel<<<(ROWS * HIDDEN / 4 + 255) / 256, 256>>>(inputs, Ahi, Alo,
                                                           ROWS * HIDDEN / 4);
    transpose_split_kernel<<<dim3(QKV_COLS / 32, HIDDEN / 32), dim3(32, 8)>>>(
        W_qkv, Wqh, Wql, HIDDEN, QKV_COLS);

    // 2) QKV projection: [4096,1024] x [4096,1024]^T -> g_qkv fp32
    gemm_tc_kernel<<<dim3(QKV_COLS / 128, ROWS / 128), 256, GSM_TOTAL>>>(
        Ahi, Alo, Wqh, Wql, qkv, QKV_COLS, HIDDEN);

    // 3) Attention -> g_attn fp32
    attn_kernel<<<dim3(SEQL / 64, BATCH * 32), 256, ATTN_SMEM_BYTES>>>();

    // 4) split attention output, transpose-split W_out
    split_kernel<<<(ROWS * ATTN_COLS / 4 + 255) / 256, 256>>>(attn, A2hi, A2lo,
                                                              ROWS * ATTN_COLS / 4);
    transpose_split_kernel<<<dim3(HIDDEN / 32, ATTN_COLS / 32), dim3(32, 8)>>>(
        W_out, Woh, Wol, ATTN_COLS, HIDDEN);

    // 5) Output projection: [4096,2048] x [1024,2048]^T -> out fp32
    gemm_tc_kernel<<<dim3(HIDDEN / 128, ROWS / 128), 256, GSM_TOTAL>>>(
        A2hi, A2lo, Woh, Wol, out, HIDDEN, ATTN_COLS);
}

// round 4
// speedup vs baseline: 2.3759x; 1.5797x over previous
#include <cuda_runtime.h>
#include <cuda_bf16.h>
#include <cstdint>

// Problem constants
#define BATCH 4
#define SEQL 1024
#define HIDDEN 1024
#define QKV_COLS 4096   // 2048 q + 1024 k + 1024 v
#define ATTN_COLS 2048  // 32*64
#define ROWS 4096       // BATCH*SEQL

// ---------------------------------------------------------------------------
// Scratch (__device__ globals; allocation-free rule)
// ---------------------------------------------------------------------------
__device__ float g_qkv[(size_t)ROWS * QKV_COLS];    // 64 MB
__device__ __nv_bfloat16 g_Ahi[(size_t)ROWS * HIDDEN];
__device__ __nv_bfloat16 g_Alo[(size_t)ROWS * HIDDEN];
__device__ __nv_bfloat16 g_Wqkv_hi[(size_t)QKV_COLS * HIDDEN];  // [N,K]
__device__ __nv_bfloat16 g_Wqkv_lo[(size_t)QKV_COLS * HIDDEN];
__device__ __nv_bfloat16 g_At2hi[(size_t)ROWS * ATTN_COLS];     // attn out split
__device__ __nv_bfloat16 g_At2lo[(size_t)ROWS * ATTN_COLS];
__device__ __nv_bfloat16 g_Wout_hi[(size_t)HIDDEN * ATTN_COLS]; // [N,K]
__device__ __nv_bfloat16 g_Wout_lo[(size_t)HIDDEN * ATTN_COLS];
// attention operand splits
__device__ __nv_bfloat16 g_Qhi[(size_t)BATCH * 32 * SEQL * 64];   // [b,h,s,d]
__device__ __nv_bfloat16 g_Qlo[(size_t)BATCH * 32 * SEQL * 64];
__device__ __nv_bfloat16 g_Khi[(size_t)BATCH * 16 * SEQL * 64];   // [b,kvh,s,d]
__device__ __nv_bfloat16 g_Klo[(size_t)BATCH * 16 * SEQL * 64];
__device__ __nv_bfloat16 g_Vthi[(size_t)BATCH * 16 * 64 * SEQL];  // [b,kvh,d,s]
__device__ __nv_bfloat16 g_Vtlo[(size_t)BATCH * 16 * 64 * SEQL];

// ---------------------------------------------------------------------------
// PTX helpers (sm_80+ only — NO tcgen05; harness targets compute_103)
// ---------------------------------------------------------------------------
__device__ __forceinline__ uint32_t smem_u32(const void* p) {
    uint32_t a;
    asm("{ .reg .u64 t; cvta.to.shared.u64 t, %1; cvt.u32.u64 %0, t; }" : "=r"(a) : "l"(p));
    return a;
}
__device__ __forceinline__ void cp16(uint32_t dst, const void* src) {
    asm volatile("cp.async.cg.shared.global [%0], [%1], 16;" :: "r"(dst), "l"(src));
}
#define CP_COMMIT() asm volatile("cp.async.commit_group;" ::: "memory")
#define CP_WAIT1()  asm volatile("cp.async.wait_group 1;" ::: "memory")

__device__ __forceinline__ uint32_t lds32(uint32_t a) {
    uint32_t v;
    asm volatile("ld.shared.b32 %0, [%1];" : "=r"(v) : "r"(a));
    return v;
}
__device__ __forceinline__ void mma_bf16(float* d, const uint32_t* a, const uint32_t* b) {
    asm volatile(
        "mma.sync.aligned.m16n8k16.row.col.f32.bf16.bf16.f32 "
        "{%0,%1,%2,%3}, {%4,%5,%6,%7}, {%8,%9}, {%0,%1,%2,%3};"
        : "+f"(d[0]), "+f"(d[1]), "+f"(d[2]), "+f"(d[3])
        : "r"(a[0]), "r"(a[1]), "r"(a[2]), "r"(a[3]), "r"(b[0]), "r"(b[1]));
}
// pack (f0 -> lo, f1 -> hi) bf16x2
__device__ __forceinline__ uint32_t cvt_bf16x2(float f0, float f1) {
    uint32_t r;
    asm("cvt.rn.bf16x2.f32 %0, %1, %2;" : "=r"(r) : "f"(f1), "f"(f0));
    return r;
}
// split a float pair into hi/lo packed bf16x2
__device__ __forceinline__ void split_pair(float f0, float f1, uint32_t& hi, uint32_t& lo) {
    hi = cvt_bf16x2(f0, f1);
    float r0 = __uint_as_float(hi << 16);
    float r1 = __uint_as_float(hi & 0xffff0000u);
    lo = cvt_bf16x2(f0 - r0, f1 - r1);
}

// ---------------------------------------------------------------------------
// HMMA GEMM (unchanged from round 3): C = A[M,K] * B[N,K]^T, bf16 3-product.
// ---------------------------------------------------------------------------
#define RSTRIDE 40
#define SLAB (128 * RSTRIDE * 2)
#define STAGE (4 * SLAB)
#define GSM_TOTAL (2 * STAGE)

__global__ __launch_bounds__(256)
void gemm_tc_kernel(const __nv_bfloat16* __restrict__ Ahi,
                    const __nv_bfloat16* __restrict__ Alo,
                    const __nv_bfloat16* __restrict__ Bhi,
                    const __nv_bfloat16* __restrict__ Blo,
                    float* __restrict__ C, int Ndim, int Kdim) {
    extern __shared__ __align__(256) char smem[];
    const uint32_t sbase = smem_u32(smem);
    const int tid = threadIdx.x;
    const int lane = tid & 31;
    const int warp = tid >> 5;
    const int wm = warp & 1;
    const int wn = warp >> 1;
    const int brow = blockIdx.y * 128;
    const int bcol = blockIdx.x * 128;

    const __nv_bfloat16* mats[4] = {Ahi, Alo, Bhi, Blo};
    const int KT = Kdim >> 5;

    auto load_stage = [&](int t) {
        const int s = t & 1;
        const int k0 = t << 5;
        const uint32_t stg = sbase + s * STAGE;
#pragma unroll
        for (int m = 0; m < 4; m++) {
            const int rowbase = (m < 2) ? brow : bcol;
            const __nv_bfloat16* base = mats[m];
#pragma unroll
            for (int u = 0; u < 2; u++) {
                int idx = tid + u * 256;
                int row = idx >> 2;
                int seg = idx & 3;
                const __nv_bfloat16* src =
                    base + (size_t)(rowbase + row) * Kdim + k0 + seg * 8;
                uint32_t dst = stg + m * SLAB + row * (RSTRIDE * 2) + seg * 16;
                cp16(dst, src);
            }
        }
        CP_COMMIT();
    };

    float acc[4][4][4];
#pragma unroll
    for (int i = 0; i < 4; i++)
#pragma unroll
        for (int j = 0; j < 4; j++)
#pragma unroll
            for (int r = 0; r < 4; r++) acc[i][j][r] = 0.f;

    load_stage(0);
    if (KT > 1) load_stage(1); else CP_COMMIT();

    const int r0 = lane >> 2;
    const int cpair = (lane & 3) * 2;

    for (int t = 0; t < KT; t++) {
        CP_WAIT1();
        __syncthreads();
        const uint32_t stg = sbase + (t & 1) * STAGE;
        const uint32_t aHi = stg + (wm * 64) * (RSTRIDE * 2);
        const uint32_t aLo = aHi + SLAB;
        const uint32_t bHi = stg + 2 * SLAB + (wn * 32) * (RSTRIDE * 2);
        const uint32_t bLo = bHi + SLAB;

#pragma unroll
        for (int ks = 0; ks < 2; ks++) {
            const uint32_t colb = ks * 32 + cpair * 2;
            uint32_t ahi[4][4], alo[4][4], bhi[4][2], blo[4][2];
#pragma unroll
            for (int mi = 0; mi < 4; mi++) {
                uint32_t rb = (mi * 16 + r0) * (RSTRIDE * 2);
                ahi[mi][0] = lds32(aHi + rb + colb);
                ahi[mi][1] = lds32(aHi + rb + 8 * (RSTRIDE * 2) + colb);
                ahi[mi][2] = lds32(aHi + rb + colb + 16);
                ahi[mi][3] = lds32(aHi + rb + 8 * (RSTRIDE * 2) + colb + 16);
                alo[mi][0] = lds32(aLo + rb + colb);
                alo[mi][1] = lds32(aLo + rb + 8 * (RSTRIDE * 2) + colb);
                alo[mi][2] = lds32(aLo + rb + colb + 16);
                alo[mi][3] = lds32(aLo + rb + 8 * (RSTRIDE * 2) + colb + 16);
            }
#pragma unroll
            for (int nj = 0; nj < 4; nj++) {
                uint32_t rb = (nj * 8 + r0) * (RSTRIDE * 2);
                bhi[nj][0] = lds32(bHi + rb + colb);
                bhi[nj][1] = lds32(bHi + rb + colb + 16);
                blo[nj][0] = lds32(bLo + rb + colb);
                blo[nj][1] = lds32(bLo + rb + colb + 16);
            }
#pragma unroll
            for (int mi = 0; mi < 4; mi++)
#pragma unroll
                for (int nj = 0; nj < 4; nj++) {
                    mma_bf16(acc[mi][nj], ahi[mi], bhi[nj]);
                    mma_bf16(acc[mi][nj], ahi[mi], blo[nj]);
                    mma_bf16(acc[mi][nj], alo[mi], bhi[nj]);
                }
        }
        __syncthreads();
        if (t + 2 < KT) load_stage(t + 2); else CP_COMMIT();
    }

#pragma unroll
    for (int mi = 0; mi < 4; mi++) {
        int row = brow + wm * 64 + mi * 16 + r0;
#pragma unroll
        for (int nj = 0; nj < 4; nj++) {
            int col = bcol + wn * 32 + nj * 8 + cpair;
            *(float2*)(C + (size_t)row * Ndim + col) =
                make_float2(acc[mi][nj][0], acc[mi][nj][1]);
            *(float2*)(C + (size_t)(row + 8) * Ndim + col) =
                make_float2(acc[mi][nj][2], acc[mi][nj][3]);
        }
    }
}

// ---------------------------------------------------------------------------
// fp32 -> bf16 hi/lo elementwise split (for GEMM A operands)
// ---------------------------------------------------------------------------
__global__ __launch_bounds__(256) void split_kernel(const float* __restrict__ x,
                                                    __nv_bfloat16* __restrict__ hi,
                                                    __nv_bfloat16* __restrict__ lo,
                                                    int n4) {
    int i = blockIdx.x * blockDim.x + threadIdx.x;
    if (i >= n4) return;
    float4 v = ((const float4*)x)[i];
    uint32_t h0, l0, h1, l1;
    split_pair(v.x, v.y, h0, l0);
    split_pair(v.z, v.w, h1, l1);
    ((uint2*)hi)[i] = make_uint2(h0, h1);
    ((uint2*)lo)[i] = make_uint2(l0, l1);
}

// ---------------------------------------------------------------------------
// W[K,N] fp32 -> Wt[N,K] bf16 hi/lo (tiled transpose + split)
// ---------------------------------------------------------------------------
__global__ __launch_bounds__(256) void transpose_split_kernel(
    const float* __restrict__ W, __nv_bfloat16* __restrict__ hi,
    __nv_bfloat16* __restrict__ lo, int K, int N) {
    __shared__ float t[32][33];
    int k0 = blockIdx.y * 32, n0 = blockIdx.x * 32;
    int tx = threadIdx.x, ty = threadIdx.y;  // (32, 8)
#pragma unroll
    for (int j = 0; j < 4; j++)
        t[ty + j * 8][tx] = W[(size_t)(k0 + ty + j * 8) * N + n0 + tx];
    __syncthreads();
#pragma unroll
    for (int j = 0; j < 4; j++) {
        float v = t[tx][ty + j * 8];
        __nv_bfloat16 h = __float2bfloat16(v);
        __nv_bfloat16 l = __float2bfloat16(v - __bfloat162float(h));
        size_t o = (size_t)(n0 + ty + j * 8) * K + k0 + tx;
        hi[o] = h;
        lo[o] = l;
    }
}

// ---------------------------------------------------------------------------
// Prep: split g_qkv into attention operand layouts
// ---------------------------------------------------------------------------
__global__ __launch_bounds__(256) void prep_q_kernel() {
    int i = blockIdx.x * 256 + threadIdx.x;       // 2M float4s
    int o = i * 4;
    int d = o & 63, s = (o >> 6) & 1023, h = (o >> 16) & 31, b = o >> 21;
    float4 v = *(const float4*)&g_qkv[((size_t)(b * 1024 + s)) * 4096 + h * 64 + d];
    uint32_t h0, l0, h1, l1;
    split_pair(v.x, v.y, h0, l0);
    split_pair(v.z, v.w, h1, l1);
    *(uint2*)&g_Qhi[o] = make_uint2(h0, h1);
    *(uint2*)&g_Qlo[o] = make_uint2(l0, l1);
}

__global__ __launch_bounds__(256) void prep_k_kernel() {
    int i = blockIdx.x * 256 + threadIdx.x;       // 1M float4s
    int o = i * 4;
    int d = o & 63, s = (o >> 6) & 1023, kvh = (o >> 16) & 15, b = o >> 20;
    float4 v = *(const float4*)&g_qkv[((size_t)(b * 1024 + s)) * 4096 + 2048 + kvh * 64 + d];
    uint32_t h0, l0, h1, l1;
    split_pair(v.x, v.y, h0, l0);
    split_pair(v.z, v.w, h1, l1);
    *(uint2*)&g_Khi[o] = make_uint2(h0, h1);
    *(uint2*)&g_Klo[o] = make_uint2(l0, l1);
}

__global__ __launch_bounds__(256) void prep_vt_kernel() {
    __shared__ float tile[64][65];
    int s0 = blockIdx.x * 64;          // 16 s-blocks
    int bk = blockIdx.y;               // b*16 + kvh
    int b = bk >> 4, kvh = bk & 15;
    int tid = threadIdx.x;
#pragma unroll
    for (int u = 0; u < 4; u++) {
        int lin = tid + u * 256;
        int row = lin >> 4, c4 = lin & 15;
        float4 v = *(const float4*)&g_qkv[((size_t)(b * 1024 + s0 + row)) * 4096 +
                                          3072 + kvh * 64 + c4 * 4];
        tile[row][c4 * 4 + 0] = v.x;
        tile[row][c4 * 4 + 1] = v.y;
        tile[row][c4 * 4 + 2] = v.z;
        tile[row][c4 * 4 + 3] = v.w;
    }
    __syncthreads();
#pragma unroll
    for (int u = 0; u < 4; u++) {
        int lin = tid + u * 256;
        int d = lin >> 4, c4 = lin & 15;
        float f0 = tile[c4 * 4 + 0][d], f1 = tile[c4 * 4 + 1][d];
        float f2 = tile[c4 * 4 + 2][d], f3 = tile[c4 * 4 + 3][d];
        uint32_t h0, l0, h1, l1;
        split_pair(f0, f1, h0, l0);
        split_pair(f2, f3, h1, l1);
        size_t o = ((size_t)bk * 64 + d) * 1024 + s0 + c4 * 4;
        *(uint2*)&g_Vthi[o] = make_uint2(h0, h1);
        *(uint2*)&g_Vtlo[o] = make_uint2(l0, l1);
    }
}

// ---------------------------------------------------------------------------
// Tensor-core flash attention, bf16 hi/lo 3-product split.
// CTA = (b,h, 128 q rows). 8 warps x 16 rows. kv tiles of 64, double buffered.
// Smem pitch 144B (72 bf16) -> conflict-free 32-bit fragment loads.
// ---------------------------------------------------------------------------
#define AP 144                    // smem pitch bytes
#define AQ_HI 0
#define AQ_LO (128 * AP)          // 18432
#define AKV0 (2 * 128 * AP)       // 36864
#define AKV_STAGE (4 * 64 * AP)   // 36864: Khi, Klo, Vthi, Vtlo slabs of 9216
#define ATT_SMEM (AKV0 + 2 * AKV_STAGE)   // 110592

__global__ __launch_bounds__(256) void attn_tc_kernel() {
    extern __shared__ __align__(256) char smem[];
    const uint32_t sbase = smem_u32(smem);
    const int tid = threadIdx.x;
    const int lane = tid & 31;
    const int warp = tid >> 5;
    const int bh = blockIdx.x;
    const int b = bh >> 5;
    const int h = bh & 31;
    const int kvh = h >> 1;
    const int qblk = (int)gridDim.y - 1 - (int)blockIdx.y;   // heavy blocks first
    const int q0 = qblk * 128;
    const int wrow = warp * 16;
    const float slope = exp2f(-0.25f * (float)(h + 1));
    const float NINF = -__int_as_float(0x7f800000);

    const __nv_bfloat16* Qhi_g = g_Qhi + ((size_t)(b * 32 + h) * 1024 + q0) * 64;
    const __nv_bfloat16* Qlo_g = g_Qlo + ((size_t)(b * 32 + h) * 1024 + q0) * 64;
    const __nv_bfloat16* Khi_g = g_Khi + (size_t)(b * 16 + kvh) * 1024 * 64;
    const __nv_bfloat16* Klo_g = g_Klo + (size_t)(b * 16 + kvh) * 1024 * 64;
    const __nv_bfloat16* Vthi_g = g_Vthi + (size_t)(b * 16 + kvh) * 64 * 1024;
    const __nv_bfloat16* Vtlo_g = g_Vtlo + (size_t)(b * 16 + kvh) * 64 * 1024;

    // Load Q (128x64 hi+lo): 2048 cp16
#pragma unroll
    for (int u = 0; u < 8; u++) {
        int idx = tid + u * 256;
        int slab = idx >> 10;          // 0: hi, 1: lo
        int rem = idx & 1023;
        int row = rem >> 3, seg = rem & 7;
        const __nv_bfloat16* src = (slab ? Qlo_g : Qhi_g) + (size_t)row * 64 + seg * 8;
        cp16(sbase + slab * (128 * AP) + row * AP + seg * 16, src);
    }
    CP_COMMIT();

    auto load_kv = [&](int t) {
        const int kv0 = t * 64;
        const uint32_t stg = sbase + AKV0 + (t & 1) * AKV_STAGE;
#pragma unroll
        for (int u = 0; u < 8; u++) {
            int idx = tid + u * 256;
            int slab = idx >> 9;            // 0 Khi, 1 Klo, 2 Vthi, 3 Vtlo
            int rem = idx & 511;
            int row = rem >> 3, seg = rem & 7;
            const __nv_bfloat16* src;
            if (slab == 0) src = Khi_g + (size_t)(kv0 + row) * 64 + seg * 8;
            else if (slab == 1) src = Klo_g + (size_t)(kv0 + row) * 64 + seg * 8;
            else if (slab == 2) src = Vthi_g + (size_t)row * 1024 + kv0 + seg * 8;
            else src = Vtlo_g + (size_t)row * 1024 + kv0 + seg * 8;
            cp16(stg + slab * (64 * AP) + row * AP + seg * 16, src);
        }
        CP_COMMIT();
    };

    const int nt = 2 * (qblk + 1);
    load_kv(0);
    load_kv(1);

    const int r = lane >> 2;
    const int tq = lane & 3;
    const int qq0 = q0 + wrow + r;
    const int qq1 = qq0 + 8;
    const uint32_t qrow_hi = sbase + (wrow + r) * AP + tq * 4;
    const uint32_t qrow_lo = qrow_hi + 128 * AP;

    float m0 = NINF, m1 = NINF, l0 = 0.f, l1 = 0.f;
    float oa[8][4];
#pragma unroll
    for (int nd = 0; nd < 8; nd++)
#pragma unroll
        for (int j = 0; j < 4; j++) oa[nd][j] = 0.f;

    for (int t = 0; t < nt; t++) {
        CP_WAIT1();
        __syncthreads();
        const int kv0 = t * 64;
        // warps fully above the diagonal in this tile skip compute
        if (kv0 <= q0 + wrow + 15) {
            const uint32_t stg = sbase + AKV0 + (t & 1) * AKV_STAGE;
            const uint32_t vbase = stg + 2 * (64 * AP);
            // --- S = Q K^T (3-product split) ---
            float sa[8][4];
#pragma unroll
            for (int nj = 0; nj < 8; nj++)
#pragma unroll
                for (int j = 0; j < 4; j++) sa[nj][j] = 0.f;
#pragma unroll
            for (int ks = 0; ks < 4; ks++) {
                const uint32_t colb = ks * 32;
                uint32_t qh[4], ql[4];
                qh[0] = lds32(qrow_hi + colb);
                qh[1] = lds32(qrow_hi + 8 * AP + colb);
                qh[2] = lds32(qrow_hi + colb + 16);
                qh[3] = lds32(qrow_hi + 8 * AP + colb + 16);
                ql[0] = lds32(qrow_lo + colb);
                ql[1] = lds32(qrow_lo + 8 * AP + colb);
                ql[2] = lds32(qrow_lo + colb + 16);
                ql[3] = lds32(qrow_lo + 8 * AP + colb + 16);
#pragma unroll
                for (int nj = 0; nj < 8; nj++) {
                    uint32_t ka = stg + (nj * 8 + r) * AP + colb + tq * 4;
                    uint32_t kh[2], kl[2];
                    kh[0] = lds32(ka);
                    kh[1] = lds32(ka + 16);
                    kl[0] = lds32(ka + 64 * AP);
                    kl[1] = lds32(ka + 64 * AP + 16);
                    mma_bf16(sa[nj], qh, kh);
                    mma_bf16(sa[nj], qh, kl);
                    mma_bf16(sa[nj], ql, kh);
                }
            }
            // --- softmax (online) ---
            float mloc0 = NINF, mloc1 = NINF;
#pragma unroll
            for (int nj = 0; nj < 8; nj++) {
                int c0 = kv0 + nj * 8 + 2 * tq;
                int c1 = c0 + 1;
                sa[nj][0] = (c0 <= qq0) ? sa[nj][0] * 0.125f + slope * (float)(c0 - qq0) : NINF;
                sa[nj][1] = (c1 <= qq0) ? sa[nj][1] * 0.125f + slope * (float)(c1 - qq0) : NINF;
                sa[nj][2] = (c0 <= qq1) ? sa[nj][2] * 0.125f + slope * (float)(c0 - qq1) : NINF;
                sa[nj][3] = (c1 <= qq1) ? sa[nj][3] * 0.125f + slope * (float)(c1 - qq1) : NINF;
                mloc0 = fmaxf(mloc0, fmaxf(sa[nj][0], sa[nj][1]));
                mloc1 = fmaxf(mloc1, fmaxf(sa[nj][2], sa[nj][3]));
            }
            mloc0 = fmaxf(mloc0, __shfl_xor_sync(0xffffffffu, mloc0, 1));
            mloc0 = fmaxf(mloc0, __shfl_xor_sync(0xffffffffu, mloc0, 2));
            mloc1 = fmaxf(mloc1, __shfl_xor_sync(0xffffffffu, mloc1, 1));
            mloc1 = fmaxf(mloc1, __shfl_xor_sync(0xffffffffu, mloc1, 2));
            float mn0 = fmaxf(m0, mloc0), mn1 = fmaxf(m1, mloc1);
            float corr0 = __expf(m0 - mn0), corr1 = __expf(m1 - mn1);
            m0 = mn0;
            m1 = mn1;
            float rs0 = 0.f, rs1 = 0.f;
            uint32_t ph[8][2], pl[8][2];
#pragma unroll
            for (int nj = 0; nj < 8; nj++) {
                float p00 = __expf(sa[nj][0] - mn0);
                float p01 = __expf(sa[nj][1] - mn0);
                float p10 = __expf(sa[nj][2] - mn1);
                float p11 = __expf(sa[nj][3] - mn1);
                rs0 += p00 + p01;
                rs1 += p10 + p11;
                split_pair(p00, p01, ph[nj][0], pl[nj][0]);
                split_pair(p10, p11, ph[nj][1], pl[nj][1]);
            }
            rs0 += __shfl_xor_sync(0xffffffffu, rs0, 1);
            rs0 += __shfl_xor_sync(0xffffffffu, rs0, 2);
            rs1 += __shfl_xor_sync(0xffffffffu, rs1, 1);
            rs1 += __shfl_xor_sync(0xffffffffu, rs1, 2);
            l0 = l0 * corr0 + rs0;
            l1 = l1 * corr1 + rs1;
#pragma unroll
            for (int nd = 0; nd < 8; nd++) {
                oa[nd][0] *= corr0;
                oa[nd][1] *= corr0;
                oa[nd][2] *= corr1;
                oa[nd][3] *= corr1;
            }
            // --- O += P V (3-product split) ---
#pragma unroll
            for (int ks = 0; ks < 4; ks++) {
                uint32_t ah[4] = {ph[2 * ks][0], ph[2 * ks][1], ph[2 * ks + 1][0], ph[2 * ks + 1][1]};
                uint32_t al[4] = {pl[2 * ks][0], pl[2 * ks][1], pl[2 * ks + 1][0], pl[2 * ks + 1][1]};
#pragma unroll
                for (int nd = 0; nd < 8; nd++) {
                    uint32_t va = vbase + (nd * 8 + r) * AP + ks * 32 + tq * 4;
                    uint32_t vh[2], vl[2];
                    vh[0] = lds32(va);
                    vh[1] = lds32(va + 16);
                    vl[0] = lds32(va + 64 * AP);
                    vl[1] = lds32(va + 64 * AP + 16);
                    mma_bf16(oa[nd], ah, vh);
                    mma_bf16(oa[nd], ah, vl);
                    mma_bf16(oa[nd], al, vh);
                }
            }
        }
        __syncthreads();
        if (t + 2 < nt) load_kv(t + 2); else CP_COMMIT();
    }

    // Epilogue: normalize and write split bf16 hi/lo directly
    const float inv0 = 1.f / l0, inv1 = 1.f / l1;
    const size_t row0 = (size_t)(b * 1024 + q0 + wrow + r) * 2048 + h * 64;
    const size_t row1 = row0 + (size_t)8 * 2048;
#pragma unroll
    for (int nd = 0; nd < 8; nd++) {
        int d0 = nd * 8 + 2 * tq;
        uint32_t hh, ll;
        split_pair(oa[nd][0] * inv0, oa[nd][1] * inv0, hh, ll);
        *(uint32_t*)&g_At2hi[row0 + d0] = hh;
        *(uint32_t*)&g_At2lo[row0 + d0] = ll;
        split_pair(oa[nd][2] * inv1, oa[nd][3] * inv1, hh, ll);
        *(uint32_t*)&g_At2hi[row1 + d0] = hh;
        *(uint32_t*)&g_At2lo[row1 + d0] = ll;
    }
}

// ---------------------------------------------------------------------------
extern "C" void kernel_launch(void* const* d_in, const int* in_sizes, int n_in,
                              void* d_out, int out_size) {
    const float* inputs = (const float*)d_in[0];  // [4,1024,1024]
    const float* W_qkv  = (const float*)d_in[1];  // [1024,4096]
    const float* W_out  = (const float*)d_in[2];  // [2048,1024]
    float* out = (float*)d_out;                   // [4,1024,1024]

    cudaFuncSetAttribute(gemm_tc_kernel, cudaFuncAttributeMaxDynamicSharedMemorySize,
                         GSM_TOTAL);
    cudaFuncSetAttribute(attn_tc_kernel, cudaFuncAttributeMaxDynamicSharedMemorySize,
                         ATT_SMEM);

    __nv_bfloat16 *Ahi, *Alo, *Wqh, *Wql, *A2hi, *A2lo, *Woh, *Wol;
    float* qkv;
    cudaGetSymbolAddress((void**)&Ahi, g_Ahi);
    cudaGetSymbolAddress((void**)&Alo, g_Alo);
    cudaGetSymbolAddress((void**)&Wqh, g_Wqkv_hi);
    cudaGetSymbolAddress((void**)&Wql, g_Wqkv_lo);
    cudaGetSymbolAddress((void**)&A2hi, g_At2hi);
    cudaGetSymbolAddress((void**)&A2lo, g_At2lo);
    cudaGetSymbolAddress((void**)&Woh, g_Wout_hi);
    cudaGetSymbolAddress((void**)&Wol, g_Wout_lo);
    cudaGetSymbolAddress((void**)&qkv, g_qkv);

    // 1) split inputs; transpose-split both weight matrices
    split_kernel<<<(ROWS * HIDDEN / 4 + 255) / 256, 256>>>(inputs, Ahi, Alo,
                                                           ROWS * HIDDEN / 4);
    transpose_split_kernel<<<dim3(QKV_COLS / 32, HIDDEN / 32), dim3(32, 8)>>>(
        W_qkv, Wqh, Wql, HIDDEN, QKV_COLS);
    transpose_split_kernel<<<dim3(HIDDEN / 32, ATTN_COLS / 32), dim3(32, 8)>>>(
        W_out, Woh, Wol, ATTN_COLS, HIDDEN);

    // 2) QKV projection -> g_qkv fp32
    gemm_tc_kernel<<<dim3(QKV_COLS / 128, ROWS / 128), 256, GSM_TOTAL>>>(
        Ahi, Alo, Wqh, Wql, qkv, QKV_COLS, HIDDEN);

    // 3) prep attention operands (split + V transpose)
    prep_q_kernel<<<(BATCH * 32 * SEQL * 64 / 4) / 256, 256>>>();
    prep_k_kernel<<<(BATCH * 16 * SEQL * 64 / 4) / 256, 256>>>();
    prep_vt_kernel<<<dim3(SEQL / 64, BATCH * 16), 256>>>();

    // 4) tensor-core attention -> g_At2hi/lo (pre-split)
    attn_tc_kernel<<<dim3(BATCH * 32, SEQL / 128), 256, ATT_SMEM>>>();

    // 5) Output projection -> out
    gemm_tc_kernel<<<dim3(HIDDEN / 128, ROWS / 128), 256, GSM_TOTAL>>>(
        A2hi, A2lo, Woh, Wol, out, HIDDEN, ATTN_COLS);
}